// round 1
// baseline (speedup 1.0000x reference)
#include <cuda_runtime.h>
#include <math.h>

#define Tn   1568
#define Dm   768
#define FFd  3072
#define NEx  8
#define HDh  64

// ---- scratch (allocation-free: __device__ globals) ----
__device__ float g_x1[Tn * Dm];        // residual after attention
__device__ float g_h2[Tn * Dm];        // LN2 output (MoE GEMM A)
__device__ float g_hbuf[Tn * FFd];     // FF1 activations, compact sorted order
__device__ int   g_top1[Tn];
__device__ int   g_perm[Tn];
__device__ int   g_off[NEx + 1];

// ============================================================
// Kernel 1: LN1 + v-projection + residual + LN2 + gating
// Attention collapses algebraically: out_head(h) = v for all h.
// 4 tokens per block, 256 threads.
// ============================================================
__global__ __launch_bounds__(256) void prep_kernel(
    const float* __restrict__ x,
    const float* __restrict__ ln1g, const float* __restrict__ ln1b,
    const float* __restrict__ Wv,   const float* __restrict__ bv,
    const float* __restrict__ ln2g, const float* __restrict__ ln2b,
    const float* __restrict__ Wg,   const float* __restrict__ bg)
{
    __shared__ float xs[4][Dm];   // raw x rows
    __shared__ float hs[4][Dm];   // ln1 out, later h2
    __shared__ float vs[4][HDh];
    __shared__ float red[16];

    const int tid  = threadIdx.x;
    const int base = blockIdx.x * 4;

    // ---- LN1 for 4 tokens ----
    for (int t = 0; t < 4; t++) {
        const float* xr = x + (size_t)(base + t) * Dm;
        float s = 0.f, ss = 0.f, lv[3];
        #pragma unroll
        for (int i = 0; i < 3; i++) {
            int c = tid + i * 256;
            float v = xr[c];
            lv[i] = v; xs[t][c] = v; s += v; ss += v * v;
        }
        #pragma unroll
        for (int o = 16; o; o >>= 1) {
            s  += __shfl_xor_sync(0xffffffffu, s,  o);
            ss += __shfl_xor_sync(0xffffffffu, ss, o);
        }
        if ((tid & 31) == 0) { red[tid >> 5] = s; red[8 + (tid >> 5)] = ss; }
        __syncthreads();
        s = 0.f; ss = 0.f;
        #pragma unroll
        for (int i = 0; i < 8; i++) { s += red[i]; ss += red[8 + i]; }
        float mu   = s * (1.f / Dm);
        float var  = ss * (1.f / Dm) - mu * mu;
        float rstd = rsqrtf(var + 1e-5f);
        #pragma unroll
        for (int i = 0; i < 3; i++) {
            int c = tid + i * 256;
            hs[t][c] = (lv[i] - mu) * rstd * ln1g[c] + ln1b[c];
        }
        __syncthreads();
    }

    // ---- v = LN1(x) @ Wv + bv  (each thread: one (token, out-col)) ----
    {
        const int t2 = tid >> 6, j = tid & 63;
        float a0 = 0.f, a1 = 0.f, a2 = 0.f, a3 = 0.f;
        for (int k = 0; k < Dm; k += 4) {
            a0 += hs[t2][k + 0] * Wv[(k + 0) * HDh + j];
            a1 += hs[t2][k + 1] * Wv[(k + 1) * HDh + j];
            a2 += hs[t2][k + 2] * Wv[(k + 2) * HDh + j];
            a3 += hs[t2][k + 3] * Wv[(k + 3) * HDh + j];
        }
        vs[t2][j] = (a0 + a1) + (a2 + a3) + bv[j];
    }
    __syncthreads();

    // ---- x1 = x + tile(v); LN2 -> h2 ----
    for (int t = 0; t < 4; t++) {
        const int tok = base + t;
        float s = 0.f, ss = 0.f, lv[3];
        #pragma unroll
        for (int i = 0; i < 3; i++) {
            int c = tid + i * 256;
            float v = xs[t][c] + vs[t][c & (HDh - 1)];
            lv[i] = v; s += v; ss += v * v;
            g_x1[(size_t)tok * Dm + c] = v;
        }
        #pragma unroll
        for (int o = 16; o; o >>= 1) {
            s  += __shfl_xor_sync(0xffffffffu, s,  o);
            ss += __shfl_xor_sync(0xffffffffu, ss, o);
        }
        if ((tid & 31) == 0) { red[tid >> 5] = s; red[8 + (tid >> 5)] = ss; }
        __syncthreads();
        s = 0.f; ss = 0.f;
        #pragma unroll
        for (int i = 0; i < 8; i++) { s += red[i]; ss += red[8 + i]; }
        float mu   = s * (1.f / Dm);
        float var  = ss * (1.f / Dm) - mu * mu;
        float rstd = rsqrtf(var + 1e-5f);
        #pragma unroll
        for (int i = 0; i < 3; i++) {
            int c = tid + i * 256;
            float h = (lv[i] - mu) * rstd * ln2g[c] + ln2b[c];
            hs[t][c] = h;
            g_h2[(size_t)tok * Dm + c] = h;
        }
        __syncthreads();
    }

    // ---- gate logits + argmax (softmax monotone -> argmax of logits) ----
    const int wid = tid >> 5, lane = tid & 31;
    if (wid < 4) {
        float lg[8];
        #pragma unroll
        for (int e = 0; e < 8; e++) lg[e] = 0.f;
        for (int k = lane; k < Dm; k += 32) {
            float h = hs[wid][k];
            #pragma unroll
            for (int e = 0; e < 8; e++) lg[e] += h * Wg[k * 8 + e];
        }
        #pragma unroll
        for (int e = 0; e < 8; e++)
            #pragma unroll
            for (int o = 16; o; o >>= 1) lg[e] += __shfl_xor_sync(0xffffffffu, lg[e], o);
        if (lane == 0) {
            float best = lg[0] + bg[0]; int bi = 0;
            #pragma unroll
            for (int e = 1; e < 8; e++) {
                float v = lg[e] + bg[e];
                if (v > best) { best = v; bi = e; }   // strict > == first-index tie-break
            }
            g_top1[base + wid] = bi;
        }
    }
}

// ============================================================
// Kernel 2: bucket tokens by expert (single block)
// ============================================================
__global__ void bucket_kernel()
{
    __shared__ int cnt[NEx];
    __shared__ int cur[NEx];
    const int tid = threadIdx.x;
    if (tid < NEx) cnt[tid] = 0;
    __syncthreads();
    for (int i = tid; i < Tn; i += 256) atomicAdd(&cnt[g_top1[i]], 1);
    __syncthreads();
    if (tid == 0) {
        int acc = 0;
        for (int e = 0; e < NEx; e++) { g_off[e] = acc; cur[e] = acc; acc += cnt[e]; }
        g_off[NEx] = acc;
    }
    __syncthreads();
    for (int i = tid; i < Tn; i += 256) {
        int e = g_top1[i];
        int p = atomicAdd(&cur[e], 1);
        g_perm[p] = i;
    }
}

__device__ __forceinline__ float gelu_exact(float v) { return v * normcdff(v); }

// ============================================================
// Kernels 3/4: per-expert GEMM, 128x128 tile, 8x8 microtile, BK=8
// IS_FF1: A = gathered g_h2 rows, epilogue = gelu -> g_hbuf (compact)
// else:   A = g_hbuf (compact), epilogue = +bias +x1 residual -> out (scatter)
// ============================================================
template<int K, int N, bool IS_FF1>
__global__ __launch_bounds__(256, 2) void moe_gemm(
    const float* __restrict__ W, const float* __restrict__ bias, float* __restrict__ out)
{
    const int e  = blockIdx.z;
    const int m0 = g_off[e];
    const int Me = g_off[e + 1] - m0;
    const int mt = blockIdx.y;
    if (mt * 128 >= Me) return;
    const int nt = blockIdx.x;

    const float* __restrict__ Bm  = W + (size_t)e * K * N + (size_t)nt * 128;
    const float* __restrict__ bia = bias + (size_t)e * N + nt * 128;

    __shared__ float As[8][128];
    __shared__ float Bs[8][128];

    const int tid  = threadIdx.x;
    const int arow = tid >> 1, aq = tid & 1;     // A-load: row 0..127, k-quad 0..1
    const int bkr  = tid >> 5, bq = tid & 31;    // B-load: k-row 0..7, n-quad 0..31
    const int ty   = tid >> 4, tx = tid & 15;    // compute grid 16x16

    const int  mloc   = mt * 128 + arow;
    const bool avalid = mloc < Me;
    const int  apos   = m0 + (avalid ? mloc : 0);
    const float* __restrict__ Arow =
        IS_FF1 ? &g_h2[(size_t)g_perm[apos] * K] : &g_hbuf[(size_t)apos * K];
    const float* __restrict__ Bp = Bm + (size_t)bkr * N + bq * 4;

    float acc[8][8];
    #pragma unroll
    for (int i = 0; i < 8; i++)
        #pragma unroll
        for (int j = 0; j < 8; j++) acc[i][j] = 0.f;

    float4 aN = *(const float4*)(Arow + aq * 4);
    if (!avalid) aN = make_float4(0.f, 0.f, 0.f, 0.f);
    float4 bN = *(const float4*)(Bp);

    for (int k0 = 0; k0 < K; k0 += 8) {
        __syncthreads();
        As[aq * 4 + 0][arow] = aN.x;
        As[aq * 4 + 1][arow] = aN.y;
        As[aq * 4 + 2][arow] = aN.z;
        As[aq * 4 + 3][arow] = aN.w;
        *(float4*)&Bs[bkr][bq * 4] = bN;
        __syncthreads();
        if (k0 + 8 < K) {   // prefetch next tile; overlaps with FFMA below
            aN = *(const float4*)(Arow + (k0 + 8) + aq * 4);
            if (!avalid) aN = make_float4(0.f, 0.f, 0.f, 0.f);
            bN = *(const float4*)(Bp + (size_t)(k0 + 8) * N);
        }
        #pragma unroll
        for (int k = 0; k < 8; k++) {
            float a[8], b[8];
            *(float4*)&a[0] = *(const float4*)&As[k][ty * 4];
            *(float4*)&a[4] = *(const float4*)&As[k][64 + ty * 4];
            *(float4*)&b[0] = *(const float4*)&Bs[k][tx * 4];
            *(float4*)&b[4] = *(const float4*)&Bs[k][64 + tx * 4];
            #pragma unroll
            for (int i = 0; i < 8; i++)
                #pragma unroll
                for (int j = 0; j < 8; j++)
                    acc[i][j] += a[i] * b[j];
        }
    }

    // ---- epilogue ----
    float bb[8];
    *(float4*)&bb[0] = *(const float4*)(bia + tx * 4);
    *(float4*)&bb[4] = *(const float4*)(bia + 64 + tx * 4);

    #pragma unroll
    for (int i = 0; i < 8; i++) {
        const int ml = mt * 128 + ((i < 4) ? (ty * 4 + i) : (64 + ty * 4 + (i - 4)));
        if (ml >= Me) continue;
        const int pos = m0 + ml;
        if (IS_FF1) {
            float* orow = &g_hbuf[(size_t)pos * N + (size_t)nt * 128];
            float4 o0, o1;
            o0.x = gelu_exact(acc[i][0] + bb[0]);
            o0.y = gelu_exact(acc[i][1] + bb[1]);
            o0.z = gelu_exact(acc[i][2] + bb[2]);
            o0.w = gelu_exact(acc[i][3] + bb[3]);
            o1.x = gelu_exact(acc[i][4] + bb[4]);
            o1.y = gelu_exact(acc[i][5] + bb[5]);
            o1.z = gelu_exact(acc[i][6] + bb[6]);
            o1.w = gelu_exact(acc[i][7] + bb[7]);
            *(float4*)&orow[tx * 4]      = o0;
            *(float4*)&orow[64 + tx * 4] = o1;
        } else {
            const int tok = g_perm[pos];
            float* orow = out + (size_t)tok * N + (size_t)nt * 128;
            const float* xrow = &g_x1[(size_t)tok * N + (size_t)nt * 128];
            float4 x0 = *(const float4*)&xrow[tx * 4];
            float4 x1v = *(const float4*)&xrow[64 + tx * 4];
            float4 o0, o1;
            o0.x = acc[i][0] + bb[0] + x0.x;
            o0.y = acc[i][1] + bb[1] + x0.y;
            o0.z = acc[i][2] + bb[2] + x0.z;
            o0.w = acc[i][3] + bb[3] + x0.w;
            o1.x = acc[i][4] + bb[4] + x1v.x;
            o1.y = acc[i][5] + bb[5] + x1v.y;
            o1.z = acc[i][6] + bb[6] + x1v.z;
            o1.w = acc[i][7] + bb[7] + x1v.w;
            *(float4*)&orow[tx * 4]      = o0;
            *(float4*)&orow[64 + tx * 4] = o1;
        }
    }
}

// ============================================================
extern "C" void kernel_launch(void* const* d_in, const int* in_sizes, int n_in,
                              void* d_out, int out_size)
{
    const float* x    = (const float*)d_in[0];
    const float* ln1g = (const float*)d_in[1];
    const float* ln1b = (const float*)d_in[2];
    // d_in[3..6] = Wq,bq,Wk,bk — provably unused (attention collapses to v)
    const float* Wv   = (const float*)d_in[7];
    const float* bv   = (const float*)d_in[8];
    const float* ln2g = (const float*)d_in[9];
    const float* ln2b = (const float*)d_in[10];
    const float* Wg   = (const float*)d_in[11];
    const float* bg   = (const float*)d_in[12];
    const float* W1   = (const float*)d_in[13];
    const float* b1   = (const float*)d_in[14];
    const float* W2   = (const float*)d_in[15];
    const float* b2   = (const float*)d_in[16];
    float* out = (float*)d_out;

    prep_kernel<<<Tn / 4, 256>>>(x, ln1g, ln1b, Wv, bv, ln2g, ln2b, Wg, bg);
    bucket_kernel<<<1, 256>>>();
    moe_gemm<Dm, FFd, true ><<<dim3(FFd / 128, 13, NEx), 256>>>(W1, b1, nullptr);
    moe_gemm<FFd, Dm, false><<<dim3(Dm  / 128, 13, NEx), 256>>>(W2, b2, out);
}

// round 2
// speedup vs baseline: 1.6311x; 1.6311x over previous
#include <cuda_runtime.h>
#include <math.h>

#define Tn   1568
#define Dm   768
#define FFd  3072
#define NEx  8
#define HDh  64
#define KSP2 4          // split-K factor for FF2

// ---- scratch (allocation-free: __device__ globals) ----
__device__ float g_x1[Tn * Dm];            // residual after attention
__device__ float g_h2[Tn * Dm];            // LN2 output (MoE GEMM A)
__device__ float g_hbuf[Tn * FFd];         // FF1 activations, compact sorted order
__device__ float g_part[KSP2 * Tn * Dm];   // FF2 split-K partials
__device__ int   g_top1[Tn];
__device__ int   g_perm[Tn];
__device__ int   g_off[NEx + 1];

// ============================================================
// Kernel 1: LN1 + v-projection + residual + LN2 + gating
// Attention collapses algebraically: out_head(h) = v for all h.
// ============================================================
__global__ __launch_bounds__(256) void prep_kernel(
    const float* __restrict__ x,
    const float* __restrict__ ln1g, const float* __restrict__ ln1b,
    const float* __restrict__ Wv,   const float* __restrict__ bv,
    const float* __restrict__ ln2g, const float* __restrict__ ln2b,
    const float* __restrict__ Wg,   const float* __restrict__ bg)
{
    __shared__ float xs[4][Dm];
    __shared__ float hs[4][Dm];
    __shared__ float vs[4][HDh];
    __shared__ float red[16];

    const int tid  = threadIdx.x;
    const int base = blockIdx.x * 4;

    for (int t = 0; t < 4; t++) {
        const float* xr = x + (size_t)(base + t) * Dm;
        float s = 0.f, ss = 0.f, lv[3];
        #pragma unroll
        for (int i = 0; i < 3; i++) {
            int c = tid + i * 256;
            float v = xr[c];
            lv[i] = v; xs[t][c] = v; s += v; ss += v * v;
        }
        #pragma unroll
        for (int o = 16; o; o >>= 1) {
            s  += __shfl_xor_sync(0xffffffffu, s,  o);
            ss += __shfl_xor_sync(0xffffffffu, ss, o);
        }
        if ((tid & 31) == 0) { red[tid >> 5] = s; red[8 + (tid >> 5)] = ss; }
        __syncthreads();
        s = 0.f; ss = 0.f;
        #pragma unroll
        for (int i = 0; i < 8; i++) { s += red[i]; ss += red[8 + i]; }
        float mu   = s * (1.f / Dm);
        float var  = ss * (1.f / Dm) - mu * mu;
        float rstd = rsqrtf(var + 1e-5f);
        #pragma unroll
        for (int i = 0; i < 3; i++) {
            int c = tid + i * 256;
            hs[t][c] = (lv[i] - mu) * rstd * ln1g[c] + ln1b[c];
        }
        __syncthreads();
    }

    {   // v = LN1(x) @ Wv + bv
        const int t2 = tid >> 6, j = tid & 63;
        float a0 = 0.f, a1 = 0.f, a2 = 0.f, a3 = 0.f;
        for (int k = 0; k < Dm; k += 4) {
            a0 += hs[t2][k + 0] * Wv[(k + 0) * HDh + j];
            a1 += hs[t2][k + 1] * Wv[(k + 1) * HDh + j];
            a2 += hs[t2][k + 2] * Wv[(k + 2) * HDh + j];
            a3 += hs[t2][k + 3] * Wv[(k + 3) * HDh + j];
        }
        vs[t2][j] = (a0 + a1) + (a2 + a3) + bv[j];
    }
    __syncthreads();

    for (int t = 0; t < 4; t++) {   // residual + LN2
        const int tok = base + t;
        float s = 0.f, ss = 0.f, lv[3];
        #pragma unroll
        for (int i = 0; i < 3; i++) {
            int c = tid + i * 256;
            float v = xs[t][c] + vs[t][c & (HDh - 1)];
            lv[i] = v; s += v; ss += v * v;
            g_x1[(size_t)tok * Dm + c] = v;
        }
        #pragma unroll
        for (int o = 16; o; o >>= 1) {
            s  += __shfl_xor_sync(0xffffffffu, s,  o);
            ss += __shfl_xor_sync(0xffffffffu, ss, o);
        }
        if ((tid & 31) == 0) { red[tid >> 5] = s; red[8 + (tid >> 5)] = ss; }
        __syncthreads();
        s = 0.f; ss = 0.f;
        #pragma unroll
        for (int i = 0; i < 8; i++) { s += red[i]; ss += red[8 + i]; }
        float mu   = s * (1.f / Dm);
        float var  = ss * (1.f / Dm) - mu * mu;
        float rstd = rsqrtf(var + 1e-5f);
        #pragma unroll
        for (int i = 0; i < 3; i++) {
            int c = tid + i * 256;
            float h = (lv[i] - mu) * rstd * ln2g[c] + ln2b[c];
            hs[t][c] = h;
            g_h2[(size_t)tok * Dm + c] = h;
        }
        __syncthreads();
    }

    // gate logits + argmax
    const int wid = tid >> 5, lane = tid & 31;
    if (wid < 4) {
        float lg[8];
        #pragma unroll
        for (int e = 0; e < 8; e++) lg[e] = 0.f;
        for (int k = lane; k < Dm; k += 32) {
            float h = hs[wid][k];
            #pragma unroll
            for (int e = 0; e < 8; e++) lg[e] += h * Wg[k * 8 + e];
        }
        #pragma unroll
        for (int e = 0; e < 8; e++)
            #pragma unroll
            for (int o = 16; o; o >>= 1) lg[e] += __shfl_xor_sync(0xffffffffu, lg[e], o);
        if (lane == 0) {
            float best = lg[0] + bg[0]; int bi = 0;
            #pragma unroll
            for (int e = 1; e < 8; e++) {
                float v = lg[e] + bg[e];
                if (v > best) { best = v; bi = e; }
            }
            g_top1[base + wid] = bi;
        }
    }
}

// ============================================================
// Kernel 2: bucket tokens by expert (single block)
// ============================================================
__global__ void bucket_kernel()
{
    __shared__ int cnt[NEx];
    __shared__ int cur[NEx];
    const int tid = threadIdx.x;
    if (tid < NEx) cnt[tid] = 0;
    __syncthreads();
    for (int i = tid; i < Tn; i += 256) atomicAdd(&cnt[g_top1[i]], 1);
    __syncthreads();
    if (tid == 0) {
        int acc = 0;
        for (int e = 0; e < NEx; e++) { g_off[e] = acc; cur[e] = acc; acc += cnt[e]; }
        g_off[NEx] = acc;
    }
    __syncthreads();
    for (int i = tid; i < Tn; i += 256) {
        int e = g_top1[i];
        int p = atomicAdd(&cur[e], 1);
        g_perm[p] = i;
    }
}

__device__ __forceinline__ float gelu_exact(float v) { return v * normcdff(v); }

// ============================================================
// Per-expert GEMM: 128x128 tile, 8x8 micro, BK=8, double-buffered smem.
// IS_FF1: A = gathered g_h2 rows, epilogue = bias+gelu -> g_hbuf (compact)
// else  : A = g_hbuf, split-K partial -> g_part (reduced later)
// ============================================================
template<int K, int N, bool IS_FF1, int KSPLIT>
__global__ __launch_bounds__(256, 2) void moe_gemm(
    const float* __restrict__ W, const float* __restrict__ bias)
{
    const int e  = blockIdx.z / KSPLIT;
    const int kc = blockIdx.z % KSPLIT;
    constexpr int KS = K / KSPLIT;

    const int m0 = g_off[e];
    const int Me = g_off[e + 1] - m0;
    const int mt = blockIdx.y;
    if (mt * 128 >= Me) return;
    const int nt = blockIdx.x;

    const float* __restrict__ Bm = W + (size_t)e * K * N + (size_t)(kc * KS) * N + (size_t)nt * 128;

    __shared__ float As[2][8][128];
    __shared__ float Bs[2][8][128];

    const int tid  = threadIdx.x;
    const int arow = tid >> 1, aq = tid & 1;
    const int bkr  = tid >> 5, bq = tid & 31;
    const int ty   = tid >> 4, tx = tid & 15;

    const int  mloc   = mt * 128 + arow;
    const bool avalid = mloc < Me;
    const int  apos   = m0 + (avalid ? mloc : 0);
    const float* __restrict__ Arow =
        (IS_FF1 ? &g_h2[(size_t)g_perm[apos] * K] : &g_hbuf[(size_t)apos * K]) + kc * KS;
    const float* __restrict__ Bp = Bm + (size_t)bkr * N + bq * 4;

    float acc[8][8];
    #pragma unroll
    for (int i = 0; i < 8; i++)
        #pragma unroll
        for (int j = 0; j < 8; j++) acc[i][j] = 0.f;

    // preload stage 0
    float4 aN = *(const float4*)(Arow + aq * 4);
    if (!avalid) aN = make_float4(0.f, 0.f, 0.f, 0.f);
    float4 bN = *(const float4*)(Bp);
    As[0][aq * 4 + 0][arow] = aN.x;
    As[0][aq * 4 + 1][arow] = aN.y;
    As[0][aq * 4 + 2][arow] = aN.z;
    As[0][aq * 4 + 3][arow] = aN.w;
    *(float4*)&Bs[0][bkr][bq * 4] = bN;
    __syncthreads();

    for (int k0 = 0; k0 < KS; k0 += 8) {
        const int  cur      = (k0 >> 3) & 1;
        const bool has_next = (k0 + 8) < KS;
        if (has_next) {   // global prefetch for next stage
            aN = *(const float4*)(Arow + (k0 + 8) + aq * 4);
            if (!avalid) aN = make_float4(0.f, 0.f, 0.f, 0.f);
            bN = *(const float4*)(Bp + (size_t)(k0 + 8) * N);
        }
        #pragma unroll
        for (int k = 0; k < 8; k++) {
            float a[8], b[8];
            *(float4*)&a[0] = *(const float4*)&As[cur][k][ty * 4];
            *(float4*)&a[4] = *(const float4*)&As[cur][k][64 + ty * 4];
            *(float4*)&b[0] = *(const float4*)&Bs[cur][k][tx * 4];
            *(float4*)&b[4] = *(const float4*)&Bs[cur][k][64 + tx * 4];
            #pragma unroll
            for (int i = 0; i < 8; i++)
                #pragma unroll
                for (int j = 0; j < 8; j++)
                    acc[i][j] += a[i] * b[j];
        }
        if (has_next) {   // stage into the other buffer
            const int nxt = cur ^ 1;
            As[nxt][aq * 4 + 0][arow] = aN.x;
            As[nxt][aq * 4 + 1][arow] = aN.y;
            As[nxt][aq * 4 + 2][arow] = aN.z;
            As[nxt][aq * 4 + 3][arow] = aN.w;
            *(float4*)&Bs[nxt][bkr][bq * 4] = bN;
        }
        __syncthreads();
    }

    // ---- epilogue ----
    if (IS_FF1) {
        float bb[8];
        *(float4*)&bb[0] = *(const float4*)(bias + (size_t)e * N + nt * 128 + tx * 4);
        *(float4*)&bb[4] = *(const float4*)(bias + (size_t)e * N + nt * 128 + 64 + tx * 4);
        #pragma unroll
        for (int i = 0; i < 8; i++) {
            const int ml = mt * 128 + ((i < 4) ? (ty * 4 + i) : (64 + ty * 4 + (i - 4)));
            if (ml >= Me) continue;
            float* orow = &g_hbuf[(size_t)(m0 + ml) * N + (size_t)nt * 128];
            float4 o0, o1;
            o0.x = gelu_exact(acc[i][0] + bb[0]);
            o0.y = gelu_exact(acc[i][1] + bb[1]);
            o0.z = gelu_exact(acc[i][2] + bb[2]);
            o0.w = gelu_exact(acc[i][3] + bb[3]);
            o1.x = gelu_exact(acc[i][4] + bb[4]);
            o1.y = gelu_exact(acc[i][5] + bb[5]);
            o1.z = gelu_exact(acc[i][6] + bb[6]);
            o1.w = gelu_exact(acc[i][7] + bb[7]);
            *(float4*)&orow[tx * 4]      = o0;
            *(float4*)&orow[64 + tx * 4] = o1;
        }
    } else {
        float* pbase = &g_part[(size_t)kc * Tn * N];
        #pragma unroll
        for (int i = 0; i < 8; i++) {
            const int ml = mt * 128 + ((i < 4) ? (ty * 4 + i) : (64 + ty * 4 + (i - 4)));
            if (ml >= Me) continue;
            float* orow = pbase + (size_t)(m0 + ml) * N + (size_t)nt * 128;
            float4 o0, o1;
            o0.x = acc[i][0]; o0.y = acc[i][1]; o0.z = acc[i][2]; o0.w = acc[i][3];
            o1.x = acc[i][4]; o1.y = acc[i][5]; o1.z = acc[i][6]; o1.w = acc[i][7];
            *(float4*)&orow[tx * 4]      = o0;
            *(float4*)&orow[64 + tx * 4] = o1;
        }
    }
}

// ============================================================
// FF2 reduce: sum split-K partials + bias + residual, scatter to out
// ============================================================
__global__ __launch_bounds__(256) void ff2_reduce(
    const float* __restrict__ b2, float* __restrict__ out)
{
    const int idx = blockIdx.x * 256 + threadIdx.x;   // float4 index
    if (idx >= Tn * Dm / 4) return;
    const int pos = idx / (Dm / 4);
    const int c   = (idx % (Dm / 4)) * 4;
    const int tok = g_perm[pos];
    const int e   = g_top1[tok];

    float4 s = *(const float4*)&g_part[(size_t)pos * Dm + c];
    #pragma unroll
    for (int kc = 1; kc < KSP2; kc++) {
        float4 p = *(const float4*)&g_part[(size_t)kc * Tn * Dm + (size_t)pos * Dm + c];
        s.x += p.x; s.y += p.y; s.z += p.z; s.w += p.w;
    }
    float4 bb = *(const float4*)&b2[(size_t)e * Dm + c];
    float4 xr = *(const float4*)&g_x1[(size_t)tok * Dm + c];
    s.x += bb.x + xr.x; s.y += bb.y + xr.y; s.z += bb.z + xr.z; s.w += bb.w + xr.w;
    *(float4*)&out[(size_t)tok * Dm + c] = s;
}

// ============================================================
extern "C" void kernel_launch(void* const* d_in, const int* in_sizes, int n_in,
                              void* d_out, int out_size)
{
    const float* x    = (const float*)d_in[0];
    const float* ln1g = (const float*)d_in[1];
    const float* ln1b = (const float*)d_in[2];
    // d_in[3..6] = Wq,bq,Wk,bk — provably unused (attention collapses to v)
    const float* Wv   = (const float*)d_in[7];
    const float* bv   = (const float*)d_in[8];
    const float* ln2g = (const float*)d_in[9];
    const float* ln2b = (const float*)d_in[10];
    const float* Wg   = (const float*)d_in[11];
    const float* bg   = (const float*)d_in[12];
    const float* W1   = (const float*)d_in[13];
    const float* b1   = (const float*)d_in[14];
    const float* W2   = (const float*)d_in[15];
    const float* b2   = (const float*)d_in[16];
    float* out = (float*)d_out;

    prep_kernel<<<Tn / 4, 256>>>(x, ln1g, ln1b, Wv, bv, ln2g, ln2b, Wg, bg);
    bucket_kernel<<<1, 256>>>();
    moe_gemm<Dm, FFd, true, 1   ><<<dim3(FFd / 128, 13, NEx),        256>>>(W1, b1);
    moe_gemm<FFd, Dm, false, KSP2><<<dim3(Dm / 128, 13, NEx * KSP2), 256>>>(W2, nullptr);
    ff2_reduce<<<(Tn * Dm / 4 + 255) / 256, 256>>>(b2, out);
}

// round 4
// speedup vs baseline: 2.2902x; 1.4041x over previous
#include <cuda_runtime.h>
#include <math.h>

#define Tn   1568
#define Dm   768
#define FFd  3072
#define NEx  8
#define HDh  64
#define KSP2 4          // split-K factor for FF2

// ---- scratch (allocation-free: __device__ globals) ----
__device__ float g_x1[Tn * Dm];            // residual after attention
__device__ float g_h2[Tn * Dm];            // LN2 output (MoE GEMM A)
__device__ float g_hbuf[Tn * FFd];         // FF1 activations, compact sorted order
__device__ float g_part[KSP2 * Tn * Dm];   // FF2 split-K partials
__device__ int   g_top1[Tn];
__device__ int   g_perm[Tn];
__device__ int   g_off[NEx + 1];

// ============================================================
// Kernel 1: LN1 + v-projection + residual + LN2 + gating
// Attention collapses algebraically: out_head(h) = v for all h.
// ============================================================
__global__ __launch_bounds__(256) void prep_kernel(
    const float* __restrict__ x,
    const float* __restrict__ ln1g, const float* __restrict__ ln1b,
    const float* __restrict__ Wv,   const float* __restrict__ bv,
    const float* __restrict__ ln2g, const float* __restrict__ ln2b,
    const float* __restrict__ Wg,   const float* __restrict__ bg)
{
    __shared__ float xs[4][Dm];
    __shared__ float hs[4][Dm];
    __shared__ float vs[4][HDh];
    __shared__ float red[16];

    const int tid  = threadIdx.x;
    const int base = blockIdx.x * 4;

    for (int t = 0; t < 4; t++) {
        const float* xr = x + (size_t)(base + t) * Dm;
        float s = 0.f, ss = 0.f, lv[3];
        #pragma unroll
        for (int i = 0; i < 3; i++) {
            int c = tid + i * 256;
            float v = xr[c];
            lv[i] = v; xs[t][c] = v; s += v; ss += v * v;
        }
        #pragma unroll
        for (int o = 16; o; o >>= 1) {
            s  += __shfl_xor_sync(0xffffffffu, s,  o);
            ss += __shfl_xor_sync(0xffffffffu, ss, o);
        }
        if ((tid & 31) == 0) { red[tid >> 5] = s; red[8 + (tid >> 5)] = ss; }
        __syncthreads();
        s = 0.f; ss = 0.f;
        #pragma unroll
        for (int i = 0; i < 8; i++) { s += red[i]; ss += red[8 + i]; }
        float mu   = s * (1.f / Dm);
        float var  = ss * (1.f / Dm) - mu * mu;
        float rstd = rsqrtf(var + 1e-5f);
        #pragma unroll
        for (int i = 0; i < 3; i++) {
            int c = tid + i * 256;
            hs[t][c] = (lv[i] - mu) * rstd * ln1g[c] + ln1b[c];
        }
        __syncthreads();
    }

    {   // v = LN1(x) @ Wv + bv
        const int t2 = tid >> 6, j = tid & 63;
        float a0 = 0.f, a1 = 0.f, a2 = 0.f, a3 = 0.f;
        for (int k = 0; k < Dm; k += 4) {
            a0 += hs[t2][k + 0] * Wv[(k + 0) * HDh + j];
            a1 += hs[t2][k + 1] * Wv[(k + 1) * HDh + j];
            a2 += hs[t2][k + 2] * Wv[(k + 2) * HDh + j];
            a3 += hs[t2][k + 3] * Wv[(k + 3) * HDh + j];
        }
        vs[t2][j] = (a0 + a1) + (a2 + a3) + bv[j];
    }
    __syncthreads();

    for (int t = 0; t < 4; t++) {   // residual + LN2
        const int tok = base + t;
        float s = 0.f, ss = 0.f, lv[3];
        #pragma unroll
        for (int i = 0; i < 3; i++) {
            int c = tid + i * 256;
            float v = xs[t][c] + vs[t][c & (HDh - 1)];
            lv[i] = v; s += v; ss += v * v;
            g_x1[(size_t)tok * Dm + c] = v;
        }
        #pragma unroll
        for (int o = 16; o; o >>= 1) {
            s  += __shfl_xor_sync(0xffffffffu, s,  o);
            ss += __shfl_xor_sync(0xffffffffu, ss, o);
        }
        if ((tid & 31) == 0) { red[tid >> 5] = s; red[8 + (tid >> 5)] = ss; }
        __syncthreads();
        s = 0.f; ss = 0.f;
        #pragma unroll
        for (int i = 0; i < 8; i++) { s += red[i]; ss += red[8 + i]; }
        float mu   = s * (1.f / Dm);
        float var  = ss * (1.f / Dm) - mu * mu;
        float rstd = rsqrtf(var + 1e-5f);
        #pragma unroll
        for (int i = 0; i < 3; i++) {
            int c = tid + i * 256;
            float h = (lv[i] - mu) * rstd * ln2g[c] + ln2b[c];
            hs[t][c] = h;
            g_h2[(size_t)tok * Dm + c] = h;
        }
        __syncthreads();
    }

    // gate logits + argmax
    const int wid = tid >> 5, lane = tid & 31;
    if (wid < 4) {
        float lg[8];
        #pragma unroll
        for (int e = 0; e < 8; e++) lg[e] = 0.f;
        for (int k = lane; k < Dm; k += 32) {
            float h = hs[wid][k];
            #pragma unroll
            for (int e = 0; e < 8; e++) lg[e] += h * Wg[k * 8 + e];
        }
        #pragma unroll
        for (int e = 0; e < 8; e++)
            #pragma unroll
            for (int o = 16; o; o >>= 1) lg[e] += __shfl_xor_sync(0xffffffffu, lg[e], o);
        if (lane == 0) {
            float best = lg[0] + bg[0]; int bi = 0;
            #pragma unroll
            for (int e = 1; e < 8; e++) {
                float v = lg[e] + bg[e];
                if (v > best) { best = v; bi = e; }
            }
            g_top1[base + wid] = bi;
        }
    }
}

// ============================================================
// Kernel 2: bucket tokens by expert (single block)
// ============================================================
__global__ void bucket_kernel()
{
    __shared__ int cnt[NEx];
    __shared__ int cur[NEx];
    const int tid = threadIdx.x;
    if (tid < NEx) cnt[tid] = 0;
    __syncthreads();
    for (int i = tid; i < Tn; i += 256) atomicAdd(&cnt[g_top1[i]], 1);
    __syncthreads();
    if (tid == 0) {
        int acc = 0;
        for (int e = 0; e < NEx; e++) { g_off[e] = acc; cur[e] = acc; acc += cnt[e]; }
        g_off[NEx] = acc;
    }
    __syncthreads();
    for (int i = tid; i < Tn; i += 256) {
        int e = g_top1[i];
        int p = atomicAdd(&cur[e], 1);
        g_perm[p] = i;
    }
}

__device__ __forceinline__ float gelu_exact(float v) { return v * normcdff(v); }

__device__ __forceinline__ unsigned f2tf32(float f) {
    unsigned r;
    asm("cvt.rna.tf32.f32 %0, %1;" : "=r"(r) : "f"(f));
    return r;
}

__device__ __forceinline__ void mma_tf32(float* c,
    unsigned a0, unsigned a1, unsigned a2, unsigned a3,
    unsigned b0, unsigned b1)
{
    asm volatile(
        "mma.sync.aligned.m16n8k8.row.col.f32.tf32.tf32.f32 "
        "{%0,%1,%2,%3}, {%4,%5,%6,%7}, {%8,%9}, {%0,%1,%2,%3};"
        : "+f"(c[0]), "+f"(c[1]), "+f"(c[2]), "+f"(c[3])
        : "r"(a0), "r"(a1), "r"(a2), "r"(a3), "r"(b0), "r"(b1));
}

// ============================================================
// TF32 tensor-core MoE GEMM: 128x128 tile, BK=16, 8 warps (32x64 each).
// SMEM stride 136 -> conflict-free mma fragment loads (banks 8c+r / 8r+c).
// IS_FF1: A = gathered g_h2, epilogue = bias+gelu -> g_hbuf (compact)
// else  : A = g_hbuf, split-K partial -> g_part
// ============================================================
#define BKt 16
#define LDA 136   // padded smem row stride (floats)

template<int K, int N, bool IS_FF1, int KSPLIT>
__global__ __launch_bounds__(256, 2) void moe_gemm_tc(
    const float* __restrict__ W, const float* __restrict__ bias)
{
    const int e  = blockIdx.z / KSPLIT;
    const int kc = blockIdx.z % KSPLIT;
    constexpr int KS = K / KSPLIT;

    const int m0 = g_off[e];
    const int Me = g_off[e + 1] - m0;
    const int mt = blockIdx.y;
    if (mt * 128 >= Me) return;
    const int nt = blockIdx.x;

    const float* __restrict__ Bm = W + (size_t)e * K * N + (size_t)(kc * KS) * N + (size_t)nt * 128;

    __shared__ float As[2][BKt][LDA];
    __shared__ float Bs[2][BKt][LDA];

    const int tid  = threadIdx.x;
    const int lane = tid & 31;
    const int w    = tid >> 5;
    const int grp  = lane >> 2, tig = lane & 3;
    const int wrow = (w & 3) * 32;       // warp M offset
    const int wcol = (w >> 2) * 64;      // warp N offset

    // ---- global loader assignments ----
    const int arow = tid & 127;          // A: row within tile
    const int aqp  = tid >> 7;           // A: k-half (0 -> k0..7, 1 -> k8..15)
    const int bkr  = tid >> 4;           // B: k row 0..15
    const int bc8  = (tid & 15) * 8;     // B: col group

    const int  mloc   = mt * 128 + arow;
    const bool avalid = mloc < Me;
    const int  apos   = m0 + (avalid ? mloc : 0);
    const float* __restrict__ Arow =
        (IS_FF1 ? &g_h2[(size_t)g_perm[apos] * K] : &g_hbuf[(size_t)apos * K]) + kc * KS;
    const float* __restrict__ Bp = Bm + (size_t)bkr * N + bc8;

    float acc[2][8][4];
    #pragma unroll
    for (int i = 0; i < 2; i++)
        #pragma unroll
        for (int j = 0; j < 8; j++)
            #pragma unroll
            for (int r = 0; r < 4; r++) acc[i][j][r] = 0.f;

    float4 aR0, aR1, bR0, bR1;

    // ---- preload stage 0 ----
    aR0 = *(const float4*)(Arow + aqp * 8);
    aR1 = *(const float4*)(Arow + aqp * 8 + 4);
    if (!avalid) { aR0 = make_float4(0,0,0,0); aR1 = make_float4(0,0,0,0); }
    bR0 = *(const float4*)(Bp);
    bR1 = *(const float4*)(Bp + 4);
    {
        const float* a0 = &aR0.x; const float* a1 = &aR1.x;
        #pragma unroll
        for (int j = 0; j < 4; j++) {
            As[0][aqp * 8 + j][arow]     = __uint_as_float(f2tf32(a0[j]));
            As[0][aqp * 8 + 4 + j][arow] = __uint_as_float(f2tf32(a1[j]));
        }
        const float* b0 = &bR0.x; const float* b1 = &bR1.x;
        #pragma unroll
        for (int j = 0; j < 4; j++) {
            Bs[0][bkr][bc8 + j]     = __uint_as_float(f2tf32(b0[j]));
            Bs[0][bkr][bc8 + 4 + j] = __uint_as_float(f2tf32(b1[j]));
        }
    }
    __syncthreads();

    for (int k0 = 0; k0 < KS; k0 += BKt) {
        const int  cur      = (k0 / BKt) & 1;
        const bool has_next = (k0 + BKt) < KS;
        if (has_next) {
            aR0 = *(const float4*)(Arow + (k0 + BKt) + aqp * 8);
            aR1 = *(const float4*)(Arow + (k0 + BKt) + aqp * 8 + 4);
            if (!avalid) { aR0 = make_float4(0,0,0,0); aR1 = make_float4(0,0,0,0); }
            bR0 = *(const float4*)(Bp + (size_t)(k0 + BKt) * N);
            bR1 = *(const float4*)(Bp + (size_t)(k0 + BKt) * N + 4);
        }

        #pragma unroll
        for (int ks = 0; ks < 2; ks++) {
            const int kk = ks * 8;
            unsigned af[2][4];
            #pragma unroll
            for (int mi = 0; mi < 2; mi++) {
                const int mb = wrow + mi * 16;
                af[mi][0] = __float_as_uint(As[cur][kk + tig    ][mb + grp    ]);
                af[mi][1] = __float_as_uint(As[cur][kk + tig    ][mb + grp + 8]);
                af[mi][2] = __float_as_uint(As[cur][kk + tig + 4][mb + grp    ]);
                af[mi][3] = __float_as_uint(As[cur][kk + tig + 4][mb + grp + 8]);
            }
            #pragma unroll
            for (int nj = 0; nj < 8; nj++) {
                const int nb = wcol + nj * 8;
                unsigned b0 = __float_as_uint(Bs[cur][kk + tig    ][nb + grp]);
                unsigned b1 = __float_as_uint(Bs[cur][kk + tig + 4][nb + grp]);
                mma_tf32(acc[0][nj], af[0][0], af[0][1], af[0][2], af[0][3], b0, b1);
                mma_tf32(acc[1][nj], af[1][0], af[1][1], af[1][2], af[1][3], b0, b1);
            }
        }

        if (has_next) {
            const int nxt = cur ^ 1;
            const float* a0 = &aR0.x; const float* a1 = &aR1.x;
            #pragma unroll
            for (int j = 0; j < 4; j++) {
                As[nxt][aqp * 8 + j][arow]     = __uint_as_float(f2tf32(a0[j]));
                As[nxt][aqp * 8 + 4 + j][arow] = __uint_as_float(f2tf32(a1[j]));
            }
            const float* b0 = &bR0.x; const float* b1 = &bR1.x;
            #pragma unroll
            for (int j = 0; j < 4; j++) {
                Bs[nxt][bkr][bc8 + j]     = __uint_as_float(f2tf32(b0[j]));
                Bs[nxt][bkr][bc8 + 4 + j] = __uint_as_float(f2tf32(b1[j]));
            }
        }
        __syncthreads();
    }

    // ---- epilogue ----
    // element (mi, nj, reg): row = wrow + mi*16 + grp + 8*(reg>>1)
    //                        col = wcol + nj*8 + 2*tig + (reg&1)
    #pragma unroll
    for (int mi = 0; mi < 2; mi++) {
        #pragma unroll
        for (int half = 0; half < 2; half++) {
            const int ml = mt * 128 + wrow + mi * 16 + grp + 8 * half;
            if (ml >= Me) continue;
            const int pos = m0 + ml;
            #pragma unroll
            for (int nj = 0; nj < 8; nj++) {
                const int col = wcol + nj * 8 + 2 * tig;
                float v0 = acc[mi][nj][2 * half];
                float v1 = acc[mi][nj][2 * half + 1];
                if (IS_FF1) {
                    const float* bia = bias + (size_t)e * N + nt * 128;
                    float2 o;
                    o.x = gelu_exact(v0 + bia[col]);
                    o.y = gelu_exact(v1 + bia[col + 1]);
                    *(float2*)&g_hbuf[(size_t)pos * N + (size_t)nt * 128 + col] = o;
                } else {
                    float2 o; o.x = v0; o.y = v1;
                    *(float2*)&g_part[(size_t)kc * Tn * N + (size_t)pos * N + (size_t)nt * 128 + col] = o;
                }
            }
        }
    }
}

// ============================================================
// FF2 reduce: sum split-K partials + bias + residual, scatter to out
// ============================================================
__global__ __launch_bounds__(256) void ff2_reduce(
    const float* __restrict__ b2, float* __restrict__ out)
{
    const int idx = blockIdx.x * 256 + threadIdx.x;   // float4 index
    if (idx >= Tn * Dm / 4) return;
    const int pos = idx / (Dm / 4);
    const int c   = (idx % (Dm / 4)) * 4;
    const int tok = g_perm[pos];
    const int e   = g_top1[tok];

    float4 s = *(const float4*)&g_part[(size_t)pos * Dm + c];
    #pragma unroll
    for (int kc = 1; kc < KSP2; kc++) {
        float4 p = *(const float4*)&g_part[(size_t)kc * Tn * Dm + (size_t)pos * Dm + c];
        s.x += p.x; s.y += p.y; s.z += p.z; s.w += p.w;
    }
    float4 bb = *(const float4*)&b2[(size_t)e * Dm + c];
    float4 xr = *(const float4*)&g_x1[(size_t)tok * Dm + c];
    s.x += bb.x + xr.x; s.y += bb.y + xr.y; s.z += bb.z + xr.z; s.w += bb.w + xr.w;
    *(float4*)&out[(size_t)tok * Dm + c] = s;
}

// ============================================================
extern "C" void kernel_launch(void* const* d_in, const int* in_sizes, int n_in,
                              void* d_out, int out_size)
{
    const float* x    = (const float*)d_in[0];
    const float* ln1g = (const float*)d_in[1];
    const float* ln1b = (const float*)d_in[2];
    // d_in[3..6] = Wq,bq,Wk,bk — provably unused (attention collapses to v)
    const float* Wv   = (const float*)d_in[7];
    const float* bv   = (const float*)d_in[8];
    const float* ln2g = (const float*)d_in[9];
    const float* ln2b = (const float*)d_in[10];
    const float* Wg   = (const float*)d_in[11];
    const float* bg   = (const float*)d_in[12];
    const float* W1   = (const float*)d_in[13];
    const float* b1   = (const float*)d_in[14];
    const float* W2   = (const float*)d_in[15];
    const float* b2   = (const float*)d_in[16];
    float* out = (float*)d_out;

    prep_kernel<<<Tn / 4, 256>>>(x, ln1g, ln1b, Wv, bv, ln2g, ln2b, Wg, bg);
    bucket_kernel<<<1, 256>>>();
    moe_gemm_tc<Dm, FFd, true, 1     ><<<dim3(FFd / 128, 13, NEx),        256>>>(W1, b1);
    moe_gemm_tc<FFd, Dm, false, KSP2><<<dim3(Dm / 128, 13, NEx * KSP2), 256>>>(W2, nullptr);
    ff2_reduce<<<(Tn * Dm / 4 + 255) / 256, 256>>>(b2, out);
}

// round 6
// speedup vs baseline: 2.7204x; 1.1878x over previous
#include <cuda_runtime.h>
#include <cstdint>
#include <math.h>

#define Tn   1568
#define Dm   768
#define FFd  3072
#define NEx  8
#define HDh  64
#define KSP2 4          // split-K factor for FF2
#define STG  3          // cp.async pipeline stages

// ---- scratch (allocation-free: __device__ globals) ----
__device__ float g_x1[Tn * Dm];            // residual after attention
__device__ float g_h2[Tn * Dm];            // LN2 output, tf32-rounded (MoE GEMM A)
__device__ float g_hbuf[Tn * FFd];         // FF1 activations, tf32-rounded, compact
__device__ float g_part[KSP2 * Tn * Dm];   // FF2 split-K partials
__device__ int   g_top1[Tn];
__device__ int   g_perm[Tn];
__device__ int   g_off[NEx + 1];

__device__ __forceinline__ unsigned f2tf32(float f) {
    unsigned r;
    asm("cvt.rna.tf32.f32 %0, %1;" : "=r"(r) : "f"(f));
    return r;
}

// ============================================================
// Kernel 1: LN1 + v-projection + residual + LN2 + gating
// Attention collapses algebraically: out_head(h) = v for all h.
// ============================================================
__global__ __launch_bounds__(256) void prep_kernel(
    const float* __restrict__ x,
    const float* __restrict__ ln1g, const float* __restrict__ ln1b,
    const float* __restrict__ Wv,   const float* __restrict__ bv,
    const float* __restrict__ ln2g, const float* __restrict__ ln2b,
    const float* __restrict__ Wg,   const float* __restrict__ bg)
{
    __shared__ float xs[4][Dm];
    __shared__ float hs[4][Dm];
    __shared__ float vs[4][HDh];
    __shared__ float red[16];

    const int tid  = threadIdx.x;
    const int base = blockIdx.x * 4;

    for (int t = 0; t < 4; t++) {
        const float* xr = x + (size_t)(base + t) * Dm;
        float s = 0.f, ss = 0.f, lv[3];
        #pragma unroll
        for (int i = 0; i < 3; i++) {
            int c = tid + i * 256;
            float v = xr[c];
            lv[i] = v; xs[t][c] = v; s += v; ss += v * v;
        }
        #pragma unroll
        for (int o = 16; o; o >>= 1) {
            s  += __shfl_xor_sync(0xffffffffu, s,  o);
            ss += __shfl_xor_sync(0xffffffffu, ss, o);
        }
        if ((tid & 31) == 0) { red[tid >> 5] = s; red[8 + (tid >> 5)] = ss; }
        __syncthreads();
        s = 0.f; ss = 0.f;
        #pragma unroll
        for (int i = 0; i < 8; i++) { s += red[i]; ss += red[8 + i]; }
        float mu   = s * (1.f / Dm);
        float var  = ss * (1.f / Dm) - mu * mu;
        float rstd = rsqrtf(var + 1e-5f);
        #pragma unroll
        for (int i = 0; i < 3; i++) {
            int c = tid + i * 256;
            hs[t][c] = (lv[i] - mu) * rstd * ln1g[c] + ln1b[c];
        }
        __syncthreads();
    }

    {   // v = LN1(x) @ Wv + bv
        const int t2 = tid >> 6, j = tid & 63;
        float a0 = 0.f, a1 = 0.f, a2 = 0.f, a3 = 0.f;
        for (int k = 0; k < Dm; k += 4) {
            a0 += hs[t2][k + 0] * Wv[(k + 0) * HDh + j];
            a1 += hs[t2][k + 1] * Wv[(k + 1) * HDh + j];
            a2 += hs[t2][k + 2] * Wv[(k + 2) * HDh + j];
            a3 += hs[t2][k + 3] * Wv[(k + 3) * HDh + j];
        }
        vs[t2][j] = (a0 + a1) + (a2 + a3) + bv[j];
    }
    __syncthreads();

    for (int t = 0; t < 4; t++) {   // residual + LN2
        const int tok = base + t;
        float s = 0.f, ss = 0.f, lv[3];
        #pragma unroll
        for (int i = 0; i < 3; i++) {
            int c = tid + i * 256;
            float v = xs[t][c] + vs[t][c & (HDh - 1)];
            lv[i] = v; s += v; ss += v * v;
            g_x1[(size_t)tok * Dm + c] = v;
        }
        #pragma unroll
        for (int o = 16; o; o >>= 1) {
            s  += __shfl_xor_sync(0xffffffffu, s,  o);
            ss += __shfl_xor_sync(0xffffffffu, ss, o);
        }
        if ((tid & 31) == 0) { red[tid >> 5] = s; red[8 + (tid >> 5)] = ss; }
        __syncthreads();
        s = 0.f; ss = 0.f;
        #pragma unroll
        for (int i = 0; i < 8; i++) { s += red[i]; ss += red[8 + i]; }
        float mu   = s * (1.f / Dm);
        float var  = ss * (1.f / Dm) - mu * mu;
        float rstd = rsqrtf(var + 1e-5f);
        #pragma unroll
        for (int i = 0; i < 3; i++) {
            int c = tid + i * 256;
            float h = (lv[i] - mu) * rstd * ln2g[c] + ln2b[c];
            hs[t][c] = h;                                  // fp32 for gating
            g_h2[(size_t)tok * Dm + c] = __uint_as_float(f2tf32(h));  // tf32-rna for GEMM A
        }
        __syncthreads();
    }

    // gate logits + argmax (fp32)
    const int wid = tid >> 5, lane = tid & 31;
    if (wid < 4) {
        float lg[8];
        #pragma unroll
        for (int e = 0; e < 8; e++) lg[e] = 0.f;
        for (int k = lane; k < Dm; k += 32) {
            float h = hs[wid][k];
            #pragma unroll
            for (int e = 0; e < 8; e++) lg[e] += h * Wg[k * 8 + e];
        }
        #pragma unroll
        for (int e = 0; e < 8; e++)
            #pragma unroll
            for (int o = 16; o; o >>= 1) lg[e] += __shfl_xor_sync(0xffffffffu, lg[e], o);
        if (lane == 0) {
            float best = lg[0] + bg[0]; int bi = 0;
            #pragma unroll
            for (int e = 1; e < 8; e++) {
                float v = lg[e] + bg[e];
                if (v > best) { best = v; bi = e; }
            }
            g_top1[base + wid] = bi;
        }
    }
}

// ============================================================
// Kernel 2: bucket tokens by expert (single block)
// ============================================================
__global__ void bucket_kernel()
{
    __shared__ int cnt[NEx];
    __shared__ int cur[NEx];
    const int tid = threadIdx.x;
    if (tid < NEx) cnt[tid] = 0;
    __syncthreads();
    for (int i = tid; i < Tn; i += 256) atomicAdd(&cnt[g_top1[i]], 1);
    __syncthreads();
    if (tid == 0) {
        int acc = 0;
        for (int e = 0; e < NEx; e++) { g_off[e] = acc; cur[e] = acc; acc += cnt[e]; }
        g_off[NEx] = acc;
    }
    __syncthreads();
    for (int i = tid; i < Tn; i += 256) {
        int e = g_top1[i];
        int p = atomicAdd(&cur[e], 1);
        g_perm[p] = i;
    }
}

__device__ __forceinline__ float gelu_exact(float v) { return v * normcdff(v); }

__device__ __forceinline__ void mma_tf32(float* c,
    unsigned a0, unsigned a1, unsigned a2, unsigned a3,
    unsigned b0, unsigned b1)
{
    asm volatile(
        "mma.sync.aligned.m16n8k8.row.col.f32.tf32.tf32.f32 "
        "{%0,%1,%2,%3}, {%4,%5,%6,%7}, {%8,%9}, {%0,%1,%2,%3};"
        : "+f"(c[0]), "+f"(c[1]), "+f"(c[2]), "+f"(c[3])
        : "r"(a0), "r"(a1), "r"(a2), "r"(a3), "r"(b0), "r"(b1));
}

__device__ __forceinline__ uint32_t smem_u32(const void* p) {
    return (uint32_t)__cvta_generic_to_shared(p);
}
__device__ __forceinline__ void cp16(uint32_t dst, const void* src) {
    asm volatile("cp.async.cg.shared.global [%0], [%1], 16;" :: "r"(dst), "l"(src));
}
__device__ __forceinline__ void cp16z(uint32_t dst, const void* src, int sz) {
    asm volatile("cp.async.cg.shared.global [%0], [%1], 16, %2;" :: "r"(dst), "l"(src), "r"(sz));
}

// ============================================================
// TF32 tensor-core MoE GEMM, cp.async 3-stage pipeline.
// Block tile 128x128, BK=16, 8 warps of 32x64.
// A smem [128][20] (m-major, pad 20 -> conflict-free frag loads)
// B smem [16][136]  (k-major, pad 136 -> conflict-free frag loads)
// Weights fed as raw f32 (HW tf32 truncation); activations pre-rounded rna.
// ============================================================
#define LDAA 20
#define LDBB 136
#define GEMM_SMEM_BYTES ((STG * 128 * LDAA + STG * 16 * LDBB) * 4)

template<int K, int N, bool IS_FF1, int KSPLIT>
__global__ __launch_bounds__(256, 2) void moe_gemm_cp(
    const float* __restrict__ W, const float* __restrict__ bias)
{
    const int e  = blockIdx.z / KSPLIT;
    const int kc = blockIdx.z % KSPLIT;
    constexpr int KS = K / KSPLIT;
    constexpr int NITER = KS / 16;

    const int m0 = g_off[e];
    const int Me = g_off[e + 1] - m0;
    const int mt = blockIdx.y;
    if (mt * 128 >= Me) return;
    const int nt = blockIdx.x;

    extern __shared__ float smem[];
    float (*As)[128][LDAA] = (float (*)[128][LDAA])smem;
    float (*Bs)[16][LDBB]  = (float (*)[16][LDBB])(smem + STG * 128 * LDAA);

    const int tid  = threadIdx.x;
    const int lane = tid & 31;
    const int w    = tid >> 5;
    const int grp  = lane >> 2, tig = lane & 3;
    const int wrow = (w & 3) * 32;
    const int wcol = (w >> 2) * 64;

    // ---- cp.async loader assignments ----
    const int ar0 = tid >> 2;            // A rows ar0, ar0+64
    const int akq = (tid & 3) * 4;       // A k-offset (floats)
    const int br0 = tid >> 5;            // B k-rows br0, br0+8
    const int bnq = (tid & 31) * 4;      // B n-offset (floats)

    const float* arowp[2]; int asz[2];
    #pragma unroll
    for (int i = 0; i < 2; i++) {
        int  mloc = mt * 128 + ar0 + i * 64;
        bool v    = mloc < Me;
        int  apos = m0 + (v ? mloc : 0);
        arowp[i] = (IS_FF1 ? &g_h2[(size_t)g_perm[apos] * K] : &g_hbuf[(size_t)apos * K])
                   + kc * KS + akq;
        asz[i] = v ? 16 : 0;
    }
    const float* __restrict__ Bbase =
        W + (size_t)e * K * N + (size_t)(kc * KS) * N + (size_t)nt * 128 + bnq;

    #define LOAD_STAGE(k0, st)                                                    \
        do {                                                                      \
            cp16z(smem_u32(&As[st][ar0][akq]),      arowp[0] + (k0), asz[0]);     \
            cp16z(smem_u32(&As[st][ar0 + 64][akq]), arowp[1] + (k0), asz[1]);     \
            cp16(smem_u32(&Bs[st][br0][bnq]),     Bbase + (size_t)((k0) + br0) * N);      \
            cp16(smem_u32(&Bs[st][br0 + 8][bnq]), Bbase + (size_t)((k0) + br0 + 8) * N);  \
            asm volatile("cp.async.commit_group;");                               \
        } while (0)

    float acc[2][8][4];
    #pragma unroll
    for (int i = 0; i < 2; i++)
        #pragma unroll
        for (int j = 0; j < 8; j++)
            #pragma unroll
            for (int r = 0; r < 4; r++) acc[i][j][r] = 0.f;

    // prologue: stages 0, 1 in flight
    LOAD_STAGE(0, 0);
    LOAD_STAGE(16, 1);
    asm volatile("cp.async.wait_group 1;");
    __syncthreads();

    for (int it = 0; it < NITER; it++) {
        const int st = it % STG;
        // prefetch stage it+2 (its smem slot was consumed in iter it-1)
        if (it + STG - 1 < NITER) {
            LOAD_STAGE((it + STG - 1) * 16, (it + STG - 1) % STG);
        } else {
            asm volatile("cp.async.commit_group;");   // keep group accounting uniform
        }

        #pragma unroll
        for (int ks = 0; ks < 2; ks++) {
            const int kk = ks * 8;
            unsigned af[2][4];
            #pragma unroll
            for (int mi = 0; mi < 2; mi++) {
                const int mb = wrow + mi * 16;
                af[mi][0] = __float_as_uint(As[st][mb + grp    ][kk + tig    ]);
                af[mi][1] = __float_as_uint(As[st][mb + grp + 8][kk + tig    ]);
                af[mi][2] = __float_as_uint(As[st][mb + grp    ][kk + tig + 4]);
                af[mi][3] = __float_as_uint(As[st][mb + grp + 8][kk + tig + 4]);
            }
            #pragma unroll
            for (int nj = 0; nj < 8; nj++) {
                const int nb = wcol + nj * 8;
                unsigned b0 = __float_as_uint(Bs[st][kk + tig    ][nb + grp]);
                unsigned b1 = __float_as_uint(Bs[st][kk + tig + 4][nb + grp]);
                mma_tf32(acc[0][nj], af[0][0], af[0][1], af[0][2], af[0][3], b0, b1);
                mma_tf32(acc[1][nj], af[1][0], af[1][1], af[1][2], af[1][3], b0, b1);
            }
        }

        asm volatile("cp.async.wait_group 1;");   // next stage resident
        __syncthreads();
    }
    #undef LOAD_STAGE

    // ---- epilogue ----
    // element (mi, nj, reg): row = wrow + mi*16 + grp + 8*(reg>>1)
    //                        col = wcol + nj*8 + 2*tig + (reg&1)
    #pragma unroll
    for (int mi = 0; mi < 2; mi++) {
        #pragma unroll
        for (int half = 0; half < 2; half++) {
            const int ml = mt * 128 + wrow + mi * 16 + grp + 8 * half;
            if (ml >= Me) continue;
            const int pos = m0 + ml;
            #pragma unroll
            for (int nj = 0; nj < 8; nj++) {
                const int col = wcol + nj * 8 + 2 * tig;
                float v0 = acc[mi][nj][2 * half];
                float v1 = acc[mi][nj][2 * half + 1];
                if (IS_FF1) {
                    const float* bia = bias + (size_t)e * N + nt * 128;
                    float2 o;
                    o.x = __uint_as_float(f2tf32(gelu_exact(v0 + bia[col])));
                    o.y = __uint_as_float(f2tf32(gelu_exact(v1 + bia[col + 1])));
                    *(float2*)&g_hbuf[(size_t)pos * N + (size_t)nt * 128 + col] = o;
                } else {
                    float2 o; o.x = v0; o.y = v1;
                    *(float2*)&g_part[(size_t)kc * Tn * N + (size_t)pos * N + (size_t)nt * 128 + col] = o;
                }
            }
        }
    }
}

// ============================================================
// FF2 reduce: sum split-K partials + bias + residual, scatter to out
// ============================================================
__global__ __launch_bounds__(256) void ff2_reduce(
    const float* __restrict__ b2, float* __restrict__ out)
{
    const int idx = blockIdx.x * 256 + threadIdx.x;   // float4 index
    if (idx >= Tn * Dm / 4) return;
    const int pos = idx / (Dm / 4);
    const int c   = (idx % (Dm / 4)) * 4;
    const int tok = g_perm[pos];
    const int e   = g_top1[tok];

    float4 s = *(const float4*)&g_part[(size_t)pos * Dm + c];
    #pragma unroll
    for (int kc = 1; kc < KSP2; kc++) {
        float4 p = *(const float4*)&g_part[(size_t)kc * Tn * Dm + (size_t)pos * Dm + c];
        s.x += p.x; s.y += p.y; s.z += p.z; s.w += p.w;
    }
    float4 bb = *(const float4*)&b2[(size_t)e * Dm + c];
    float4 xr = *(const float4*)&g_x1[(size_t)tok * Dm + c];
    s.x += bb.x + xr.x; s.y += bb.y + xr.y; s.z += bb.z + xr.z; s.w += bb.w + xr.w;
    *(float4*)&out[(size_t)tok * Dm + c] = s;
}

// ============================================================
extern "C" void kernel_launch(void* const* d_in, const int* in_sizes, int n_in,
                              void* d_out, int out_size)
{
    const float* x    = (const float*)d_in[0];
    const float* ln1g = (const float*)d_in[1];
    const float* ln1b = (const float*)d_in[2];
    // d_in[3..6] = Wq,bq,Wk,bk — provably unused (attention collapses to v)
    const float* Wv   = (const float*)d_in[7];
    const float* bv   = (const float*)d_in[8];
    const float* ln2g = (const float*)d_in[9];
    const float* ln2b = (const float*)d_in[10];
    const float* Wg   = (const float*)d_in[11];
    const float* bg   = (const float*)d_in[12];
    const float* W1   = (const float*)d_in[13];
    const float* b1   = (const float*)d_in[14];
    const float* W2   = (const float*)d_in[15];
    const float* b2   = (const float*)d_in[16];
    float* out = (float*)d_out;

    // idempotent, host-side, not a stream op — safe under graph capture,
    // and unconditional (no static guards per harness rules).
    cudaFuncSetAttribute(moe_gemm_cp<Dm, FFd, true, 1>,
                         cudaFuncAttributeMaxDynamicSharedMemorySize, GEMM_SMEM_BYTES);
    cudaFuncSetAttribute(moe_gemm_cp<FFd, Dm, false, KSP2>,
                         cudaFuncAttributeMaxDynamicSharedMemorySize, GEMM_SMEM_BYTES);

    prep_kernel<<<Tn / 4, 256>>>(x, ln1g, ln1b, Wv, bv, ln2g, ln2b, Wg, bg);
    bucket_kernel<<<1, 256>>>();
    moe_gemm_cp<Dm, FFd, true, 1>
        <<<dim3(FFd / 128, 13, NEx), 256, GEMM_SMEM_BYTES>>>(W1, b1);
    moe_gemm_cp<FFd, Dm, false, KSP2>
        <<<dim3(Dm / 128, 13, NEx * KSP2), 256, GEMM_SMEM_BYTES>>>(W2, nullptr);
    ff2_reduce<<<(Tn * Dm / 4 + 255) / 256, 256>>>(b2, out);
}

// round 7
// speedup vs baseline: 4.2134x; 1.5488x over previous
#include <cuda_runtime.h>
#include <cstdint>
#include <math.h>

#define Tn   1568
#define Dm   768
#define FFd  3072
#define NEx  8
#define HDh  64
#define KSP2 3          // split-K factor for FF2 (288 CTAs ~= one full wave)
#define STG  4          // cp.async pipeline stages (mainloop unrolled x4)

// ---- scratch (allocation-free: __device__ globals) ----
__device__ float g_x1[Tn * Dm];            // residual after attention
__device__ float g_h2[Tn * Dm];            // LN2 output, tf32-rounded (MoE GEMM A)
__device__ float g_hbuf[Tn * FFd];         // FF1 activations, tf32-rounded, compact
__device__ float g_part[KSP2 * Tn * Dm];   // FF2 split-K partials
__device__ int   g_top1[Tn];
__device__ int   g_perm[Tn];
__device__ int   g_off[NEx + 1];

__device__ __forceinline__ unsigned f2tf32(float f) {
    unsigned r;
    asm("cvt.rna.tf32.f32 %0, %1;" : "=r"(r) : "f"(f));
    return r;
}

// ============================================================
// Kernel 1: LN1 + v-projection + residual + LN2 + gating
// Attention collapses algebraically: out_head(h) = v for all h.
// ============================================================
__global__ __launch_bounds__(256) void prep_kernel(
    const float* __restrict__ x,
    const float* __restrict__ ln1g, const float* __restrict__ ln1b,
    const float* __restrict__ Wv,   const float* __restrict__ bv,
    const float* __restrict__ ln2g, const float* __restrict__ ln2b,
    const float* __restrict__ Wg,   const float* __restrict__ bg)
{
    __shared__ float xs[4][Dm];
    __shared__ float hs[4][Dm];
    __shared__ float vs[4][HDh];
    __shared__ float red[16];

    const int tid  = threadIdx.x;
    const int base = blockIdx.x * 4;

    for (int t = 0; t < 4; t++) {
        const float* xr = x + (size_t)(base + t) * Dm;
        float s = 0.f, ss = 0.f, lv[3];
        #pragma unroll
        for (int i = 0; i < 3; i++) {
            int c = tid + i * 256;
            float v = xr[c];
            lv[i] = v; xs[t][c] = v; s += v; ss += v * v;
        }
        #pragma unroll
        for (int o = 16; o; o >>= 1) {
            s  += __shfl_xor_sync(0xffffffffu, s,  o);
            ss += __shfl_xor_sync(0xffffffffu, ss, o);
        }
        if ((tid & 31) == 0) { red[tid >> 5] = s; red[8 + (tid >> 5)] = ss; }
        __syncthreads();
        s = 0.f; ss = 0.f;
        #pragma unroll
        for (int i = 0; i < 8; i++) { s += red[i]; ss += red[8 + i]; }
        float mu   = s * (1.f / Dm);
        float var  = ss * (1.f / Dm) - mu * mu;
        float rstd = rsqrtf(var + 1e-5f);
        #pragma unroll
        for (int i = 0; i < 3; i++) {
            int c = tid + i * 256;
            hs[t][c] = (lv[i] - mu) * rstd * ln1g[c] + ln1b[c];
        }
        __syncthreads();
    }

    {   // v = LN1(x) @ Wv + bv
        const int t2 = tid >> 6, j = tid & 63;
        float a0 = 0.f, a1 = 0.f, a2 = 0.f, a3 = 0.f;
        for (int k = 0; k < Dm; k += 4) {
            a0 += hs[t2][k + 0] * Wv[(k + 0) * HDh + j];
            a1 += hs[t2][k + 1] * Wv[(k + 1) * HDh + j];
            a2 += hs[t2][k + 2] * Wv[(k + 2) * HDh + j];
            a3 += hs[t2][k + 3] * Wv[(k + 3) * HDh + j];
        }
        vs[t2][j] = (a0 + a1) + (a2 + a3) + bv[j];
    }
    __syncthreads();

    for (int t = 0; t < 4; t++) {   // residual + LN2
        const int tok = base + t;
        float s = 0.f, ss = 0.f, lv[3];
        #pragma unroll
        for (int i = 0; i < 3; i++) {
            int c = tid + i * 256;
            float v = xs[t][c] + vs[t][c & (HDh - 1)];
            lv[i] = v; s += v; ss += v * v;
            g_x1[(size_t)tok * Dm + c] = v;
        }
        #pragma unroll
        for (int o = 16; o; o >>= 1) {
            s  += __shfl_xor_sync(0xffffffffu, s,  o);
            ss += __shfl_xor_sync(0xffffffffu, ss, o);
        }
        if ((tid & 31) == 0) { red[tid >> 5] = s; red[8 + (tid >> 5)] = ss; }
        __syncthreads();
        s = 0.f; ss = 0.f;
        #pragma unroll
        for (int i = 0; i < 8; i++) { s += red[i]; ss += red[8 + i]; }
        float mu   = s * (1.f / Dm);
        float var  = ss * (1.f / Dm) - mu * mu;
        float rstd = rsqrtf(var + 1e-5f);
        #pragma unroll
        for (int i = 0; i < 3; i++) {
            int c = tid + i * 256;
            float h = (lv[i] - mu) * rstd * ln2g[c] + ln2b[c];
            hs[t][c] = h;                                  // fp32 for gating
            g_h2[(size_t)tok * Dm + c] = __uint_as_float(f2tf32(h));  // tf32-rna for GEMM A
        }
        __syncthreads();
    }

    // gate logits + argmax (fp32)
    const int wid = tid >> 5, lane = tid & 31;
    if (wid < 4) {
        float lg[8];
        #pragma unroll
        for (int e = 0; e < 8; e++) lg[e] = 0.f;
        for (int k = lane; k < Dm; k += 32) {
            float h = hs[wid][k];
            #pragma unroll
            for (int e = 0; e < 8; e++) lg[e] += h * Wg[k * 8 + e];
        }
        #pragma unroll
        for (int e = 0; e < 8; e++)
            #pragma unroll
            for (int o = 16; o; o >>= 1) lg[e] += __shfl_xor_sync(0xffffffffu, lg[e], o);
        if (lane == 0) {
            float best = lg[0] + bg[0]; int bi = 0;
            #pragma unroll
            for (int e = 1; e < 8; e++) {
                float v = lg[e] + bg[e];
                if (v > best) { best = v; bi = e; }
            }
            g_top1[base + wid] = bi;
        }
    }
}

// ============================================================
// Kernel 2: bucket tokens by expert (single block)
// ============================================================
__global__ void bucket_kernel()
{
    __shared__ int cnt[NEx];
    __shared__ int cur[NEx];
    const int tid = threadIdx.x;
    if (tid < NEx) cnt[tid] = 0;
    __syncthreads();
    for (int i = tid; i < Tn; i += 256) atomicAdd(&cnt[g_top1[i]], 1);
    __syncthreads();
    if (tid == 0) {
        int acc = 0;
        for (int e = 0; e < NEx; e++) { g_off[e] = acc; cur[e] = acc; acc += cnt[e]; }
        g_off[NEx] = acc;
    }
    __syncthreads();
    for (int i = tid; i < Tn; i += 256) {
        int e = g_top1[i];
        int p = atomicAdd(&cur[e], 1);
        g_perm[p] = i;
    }
}

__device__ __forceinline__ float gelu_exact(float v) { return v * normcdff(v); }

__device__ __forceinline__ void mma_tf32(float* c,
    unsigned a0, unsigned a1, unsigned a2, unsigned a3,
    unsigned b0, unsigned b1)
{
    asm volatile(
        "mma.sync.aligned.m16n8k8.row.col.f32.tf32.tf32.f32 "
        "{%0,%1,%2,%3}, {%4,%5,%6,%7}, {%8,%9}, {%0,%1,%2,%3};"
        : "+f"(c[0]), "+f"(c[1]), "+f"(c[2]), "+f"(c[3])
        : "r"(a0), "r"(a1), "r"(a2), "r"(a3), "r"(b0), "r"(b1));
}

__device__ __forceinline__ uint32_t smem_u32(const void* p) {
    return (uint32_t)__cvta_generic_to_shared(p);
}
__device__ __forceinline__ void cp16(uint32_t dst, const void* src) {
    asm volatile("cp.async.cg.shared.global [%0], [%1], 16;" :: "r"(dst), "l"(src));
}
__device__ __forceinline__ void cp16z(uint32_t dst, const void* src, int sz) {
    asm volatile("cp.async.cg.shared.global [%0], [%1], 16, %2;" :: "r"(dst), "l"(src), "r"(sz));
}

// ============================================================
// TF32 tensor-core MoE GEMM, cp.async 4-stage pipeline, mainloop
// unrolled x4 so all smem stage indices are compile-time constants.
// Block tile 128x128, BK=16, 8 warps of 32x64.
// A smem [128][20] (m-major, pad 20 -> conflict-free frag loads)
// B smem [16][136]  (k-major, pad 136 -> conflict-free frag loads)
// Weights fed as raw f32 (HW tf32 truncation); activations pre-rounded rna.
// ============================================================
#define LDAA 20
#define LDBB 136
#define GEMM_SMEM_BYTES ((STG * 128 * LDAA + STG * 16 * LDBB) * 4)

template<int K, int N, bool IS_FF1, int KSPLIT>
__global__ __launch_bounds__(256, 2) void moe_gemm_cp(
    const float* __restrict__ W, const float* __restrict__ bias)
{
    const int e  = blockIdx.z / KSPLIT;
    const int kc = blockIdx.z % KSPLIT;
    constexpr int KS = K / KSPLIT;
    constexpr int NITER = KS / 16;
    static_assert(NITER % STG == 0, "unroll requires NITER % STG == 0");

    const int m0 = g_off[e];
    const int Me = g_off[e + 1] - m0;
    const int mt = blockIdx.y;
    if (mt * 128 >= Me) return;
    const int nt = blockIdx.x;

    extern __shared__ float smem[];
    float (*As)[128][LDAA] = (float (*)[128][LDAA])smem;
    float (*Bs)[16][LDBB]  = (float (*)[16][LDBB])(smem + STG * 128 * LDAA);

    const int tid  = threadIdx.x;
    const int lane = tid & 31;
    const int w    = tid >> 5;
    const int grp  = lane >> 2, tig = lane & 3;
    const int wrow = (w & 3) * 32;
    const int wcol = (w >> 2) * 64;

    // ---- cp.async loader assignments ----
    const int ar0 = tid >> 2;            // A rows ar0, ar0+64
    const int akq = (tid & 3) * 4;       // A k-offset (floats)
    const int br0 = tid >> 5;            // B k-rows br0, br0+8
    const int bnq = (tid & 31) * 4;      // B n-offset (floats)

    const float* arowp[2]; int asz[2];
    #pragma unroll
    for (int i = 0; i < 2; i++) {
        int  mloc = mt * 128 + ar0 + i * 64;
        bool v    = mloc < Me;
        int  apos = m0 + (v ? mloc : 0);
        arowp[i] = (IS_FF1 ? &g_h2[(size_t)g_perm[apos] * K] : &g_hbuf[(size_t)apos * K])
                   + kc * KS + akq;
        asz[i] = v ? 16 : 0;
    }
    const float* __restrict__ Bbase =
        W + (size_t)e * K * N + (size_t)(kc * KS) * N + (size_t)nt * 128 + bnq;

    #define LOAD_STAGE(k0, st)                                                    \
        do {                                                                      \
            cp16z(smem_u32(&As[st][ar0][akq]),      arowp[0] + (k0), asz[0]);     \
            cp16z(smem_u32(&As[st][ar0 + 64][akq]), arowp[1] + (k0), asz[1]);     \
            cp16(smem_u32(&Bs[st][br0][bnq]),     Bbase + (size_t)((k0) + br0) * N);      \
            cp16(smem_u32(&Bs[st][br0 + 8][bnq]), Bbase + (size_t)((k0) + br0 + 8) * N);  \
            asm volatile("cp.async.commit_group;");                               \
        } while (0)

    float acc[2][8][4];
    #pragma unroll
    for (int i = 0; i < 2; i++)
        #pragma unroll
        for (int j = 0; j < 8; j++)
            #pragma unroll
            for (int r = 0; r < 4; r++) acc[i][j][r] = 0.f;

    // prologue: stages 0..STG-2 in flight
    LOAD_STAGE(0, 0);
    LOAD_STAGE(16, 1);
    LOAD_STAGE(32, 2);
    asm volatile("cp.async.wait_group %0;" :: "n"(STG - 2));
    __syncthreads();

    for (int it = 0; it < NITER; it += STG) {
        #pragma unroll
        for (int u = 0; u < STG; u++) {
            const int st  = u;                   // (it+u) % STG — static
            const int pf  = (u + STG - 1) % STG; // prefetch slot — static
            const int kit = it + u;

            if (kit + STG - 1 < NITER) {
                LOAD_STAGE((kit + STG - 1) * 16, pf);
            } else {
                asm volatile("cp.async.commit_group;");
            }

            #pragma unroll
            for (int ks = 0; ks < 2; ks++) {
                const int kk = ks * 8;
                unsigned af[2][4];
                #pragma unroll
                for (int mi = 0; mi < 2; mi++) {
                    const int mb = wrow + mi * 16;
                    af[mi][0] = __float_as_uint(As[st][mb + grp    ][kk + tig    ]);
                    af[mi][1] = __float_as_uint(As[st][mb + grp + 8][kk + tig    ]);
                    af[mi][2] = __float_as_uint(As[st][mb + grp    ][kk + tig + 4]);
                    af[mi][3] = __float_as_uint(As[st][mb + grp + 8][kk + tig + 4]);
                }
                #pragma unroll
                for (int nj = 0; nj < 8; nj++) {
                    const int nb = wcol + nj * 8;
                    unsigned b0 = __float_as_uint(Bs[st][kk + tig    ][nb + grp]);
                    unsigned b1 = __float_as_uint(Bs[st][kk + tig + 4][nb + grp]);
                    mma_tf32(acc[0][nj], af[0][0], af[0][1], af[0][2], af[0][3], b0, b1);
                    mma_tf32(acc[1][nj], af[1][0], af[1][1], af[1][2], af[1][3], b0, b1);
                }
            }

            asm volatile("cp.async.wait_group %0;" :: "n"(STG - 2));
            __syncthreads();
        }
    }
    #undef LOAD_STAGE

    // ---- epilogue ----
    // element (mi, nj, reg): row = wrow + mi*16 + grp + 8*(reg>>1)
    //                        col = wcol + nj*8 + 2*tig + (reg&1)
    #pragma unroll
    for (int mi = 0; mi < 2; mi++) {
        #pragma unroll
        for (int half = 0; half < 2; half++) {
            const int ml = mt * 128 + wrow + mi * 16 + grp + 8 * half;
            if (ml >= Me) continue;
            const int pos = m0 + ml;
            #pragma unroll
            for (int nj = 0; nj < 8; nj++) {
                const int col = wcol + nj * 8 + 2 * tig;
                float v0 = acc[mi][nj][2 * half];
                float v1 = acc[mi][nj][2 * half + 1];
                if (IS_FF1) {
                    const float* bia = bias + (size_t)e * N + nt * 128;
                    float2 o;
                    o.x = __uint_as_float(f2tf32(gelu_exact(v0 + bia[col])));
                    o.y = __uint_as_float(f2tf32(gelu_exact(v1 + bia[col + 1])));
                    *(float2*)&g_hbuf[(size_t)pos * N + (size_t)nt * 128 + col] = o;
                } else {
                    float2 o; o.x = v0; o.y = v1;
                    *(float2*)&g_part[(size_t)kc * Tn * N + (size_t)pos * N + (size_t)nt * 128 + col] = o;
                }
            }
        }
    }
}

// ============================================================
// FF2 reduce: sum split-K partials + bias + residual, scatter to out
// ============================================================
__global__ __launch_bounds__(256) void ff2_reduce(
    const float* __restrict__ b2, float* __restrict__ out)
{
    const int idx = blockIdx.x * 256 + threadIdx.x;   // float4 index
    if (idx >= Tn * Dm / 4) return;
    const int pos = idx / (Dm / 4);
    const int c   = (idx % (Dm / 4)) * 4;
    const int tok = g_perm[pos];
    const int e   = g_top1[tok];

    float4 s = *(const float4*)&g_part[(size_t)pos * Dm + c];
    #pragma unroll
    for (int kc = 1; kc < KSP2; kc++) {
        float4 p = *(const float4*)&g_part[(size_t)kc * Tn * Dm + (size_t)pos * Dm + c];
        s.x += p.x; s.y += p.y; s.z += p.z; s.w += p.w;
    }
    float4 bb = *(const float4*)&b2[(size_t)e * Dm + c];
    float4 xr = *(const float4*)&g_x1[(size_t)tok * Dm + c];
    s.x += bb.x + xr.x; s.y += bb.y + xr.y; s.z += bb.z + xr.z; s.w += bb.w + xr.w;
    *(float4*)&out[(size_t)tok * Dm + c] = s;
}

// ============================================================
extern "C" void kernel_launch(void* const* d_in, const int* in_sizes, int n_in,
                              void* d_out, int out_size)
{
    const float* x    = (const float*)d_in[0];
    const float* ln1g = (const float*)d_in[1];
    const float* ln1b = (const float*)d_in[2];
    // d_in[3..6] = Wq,bq,Wk,bk — provably unused (attention collapses to v)
    const float* Wv   = (const float*)d_in[7];
    const float* bv   = (const float*)d_in[8];
    const float* ln2g = (const float*)d_in[9];
    const float* ln2b = (const float*)d_in[10];
    const float* Wg   = (const float*)d_in[11];
    const float* bg   = (const float*)d_in[12];
    const float* W1   = (const float*)d_in[13];
    const float* b1   = (const float*)d_in[14];
    const float* W2   = (const float*)d_in[15];
    const float* b2   = (const float*)d_in[16];
    float* out = (float*)d_out;

    // idempotent, host-side, not a stream op — safe under graph capture.
    cudaFuncSetAttribute(moe_gemm_cp<Dm, FFd, true, 1>,
                         cudaFuncAttributeMaxDynamicSharedMemorySize, GEMM_SMEM_BYTES);
    cudaFuncSetAttribute(moe_gemm_cp<FFd, Dm, false, KSP2>,
                         cudaFuncAttributeMaxDynamicSharedMemorySize, GEMM_SMEM_BYTES);

    prep_kernel<<<Tn / 4, 256>>>(x, ln1g, ln1b, Wv, bv, ln2g, ln2b, Wg, bg);
    bucket_kernel<<<1, 256>>>();
    moe_gemm_cp<Dm, FFd, true, 1>
        <<<dim3(FFd / 128, 13, NEx), 256, GEMM_SMEM_BYTES>>>(W1, b1);
    moe_gemm_cp<FFd, Dm, false, KSP2>
        <<<dim3(Dm / 128, 13, NEx * KSP2), 256, GEMM_SMEM_BYTES>>>(W2, nullptr);
    ff2_reduce<<<(Tn * Dm / 4 + 255) / 256, 256>>>(b2, out);
}